// round 6
// baseline (speedup 1.0000x reference)
#include <cuda_runtime.h>
#include <math.h>

#define TT 2048
#define DD 3584
#define NH 28
#define KH 4
#define HD 128
#define GQ 7

// scratch (static __device__ arrays: allocation-free)
__device__ float g_q[(size_t)NH * TT * HD];
__device__ float g_k[(size_t)KH * TT * HD];
__device__ float g_v[(size_t)KH * TT * HD];
__device__ float g_ctx[(size_t)TT * DD];

// ---------------------------------------------------------------------------
// QKV projection: out[z][t][h] = sum_d x[t][d] * W[z][d][h] + b[z][h]
// z in [0,28) -> Q, [28,32) -> K, [32,36) -> V
// Tile: BM=64, BN=128 (full head), BK=16. 256 threads, 4x8 per thread.
// ---------------------------------------------------------------------------
__global__ __launch_bounds__(256) void qkv_proj_kernel(
    const float* __restrict__ x,
    const float* __restrict__ wq, const float* __restrict__ bq,
    const float* __restrict__ wk, const float* __restrict__ bk,
    const float* __restrict__ wv, const float* __restrict__ bv)
{
    __shared__ float Xs[16][68];      // [kk][row], padded
    __shared__ float Ws[16 * 128];    // [kk][h]

    int z = blockIdx.y;
    const float* w; const float* b; float* out;
    if (z < NH)           { w = wq + (size_t)z * DD * HD;        b = bq + z * HD;        out = g_q + (size_t)z * TT * HD; }
    else if (z < NH + KH) { int c = z - NH;      w = wk + (size_t)c * DD * HD; b = bk + c * HD; out = g_k + (size_t)c * TT * HD; }
    else                  { int c = z - NH - KH; w = wv + (size_t)c * DD * HD; b = bv + c * HD; out = g_v + (size_t)c * TT * HD; }

    int t0 = blockIdx.x * 64;
    int tid = threadIdx.x;
    int ty = tid >> 4, tx = tid & 15;

    float acc[4][8];
#pragma unroll
    for (int i = 0; i < 4; i++)
#pragma unroll
        for (int j = 0; j < 8; j++) acc[i][j] = 0.f;

    int xrow = tid >> 2, xc4 = tid & 3;
    const float4* x4 = (const float4*)x;
    float4* Ws4 = (float4*)Ws;

    for (int k0 = 0; k0 < DD; k0 += 16) {
        // X tile: 64 rows x 16 d, transposed into Xs[kk][row]
        float4 xv = x4[((size_t)(t0 + xrow) * DD + k0) / 4 + xc4];
        Xs[xc4 * 4 + 0][xrow] = xv.x;
        Xs[xc4 * 4 + 1][xrow] = xv.y;
        Xs[xc4 * 4 + 2][xrow] = xv.z;
        Xs[xc4 * 4 + 3][xrow] = xv.w;
        // W tile: rows k0..k0+15 contiguous (row-major [D][H])
        const float4* w4 = (const float4*)(w + (size_t)k0 * HD);
#pragma unroll
        for (int it = 0; it < 2; it++) {
            int l = tid + it * 256;
            Ws4[l] = w4[l];
        }
        __syncthreads();
#pragma unroll
        for (int kk = 0; kk < 16; kk++) {
            float4 a  = *(const float4*)&Xs[kk][ty * 4];
            float4 b0 = *(const float4*)&Ws[kk * 128 + tx * 4];
            float4 b1 = *(const float4*)&Ws[kk * 128 + 64 + tx * 4];
            float av[4] = {a.x, a.y, a.z, a.w};
            float bv8[8] = {b0.x, b0.y, b0.z, b0.w, b1.x, b1.y, b1.z, b1.w};
#pragma unroll
            for (int i = 0; i < 4; i++)
#pragma unroll
                for (int j = 0; j < 8; j++) acc[i][j] += av[i] * bv8[j];
        }
        __syncthreads();
    }

    float bb[8];
#pragma unroll
    for (int j = 0; j < 4; j++) { bb[j] = b[tx * 4 + j]; bb[4 + j] = b[64 + tx * 4 + j]; }
#pragma unroll
    for (int i = 0; i < 4; i++) {
        int t = t0 + ty * 4 + i;
        float4 o0 = make_float4(acc[i][0] + bb[0], acc[i][1] + bb[1], acc[i][2] + bb[2], acc[i][3] + bb[3]);
        float4 o1 = make_float4(acc[i][4] + bb[4], acc[i][5] + bb[5], acc[i][6] + bb[6], acc[i][7] + bb[7]);
        *(float4*)&out[(size_t)t * HD + tx * 4] = o0;
        *(float4*)&out[(size_t)t * HD + 64 + tx * 4] = o1;
    }
}

// ---------------------------------------------------------------------------
// RoPE in-place on g_q (with 1/sqrt(H) scale) and g_k. fp64 angle math.
// grid: (T, NH+KH), block 64
// ---------------------------------------------------------------------------
__global__ void rope_kernel(const int* __restrict__ positions)
{
    int t = blockIdx.x;
    int hidx = blockIdx.y;
    int i = threadIdx.x;  // 0..63

    float* base; float scale;
    if (hidx < NH) { base = g_q + ((size_t)hidx * TT + t) * HD; scale = 0.08838834764831845f; }
    else           { base = g_k + ((size_t)(hidx - NH) * TT + t) * HD; scale = 1.0f; }

    int pos = positions[t];
    double inv_freq = pow(1000000.0, -(double)(2 * i) / 128.0);
    double ang = (double)pos * inv_freq;
    double sd, cd;
    sincos(ang, &sd, &cd);
    float c = (float)cd, s = (float)sd;
    float x1 = base[i], x2 = base[i + 64];
    base[i]      = (x1 * c - x2 * s) * scale;
    base[i + 64] = (x2 * c + x1 * s) * scale;
}

// ---------------------------------------------------------------------------
// Flash attention, fp32. grid (T/64, NH), block 256.
// Q,K shared transposed [h][row] (stride 68) for conflict-free LDS.128 in QK^T.
// Online softmax: each warp owns S-rows [8w, 8w+8) (warp-local stats).
// ---------------------------------------------------------------------------
#define FLASH_SMEM ((128 * 68 * 2 + 64 * 128 + 64 * 68 + 192) * 4)

__global__ __launch_bounds__(256) void flash_kernel()
{
    extern __shared__ float sm[];
    float* Qs   = sm;                    // 128*68  (transposed, pad)
    float* Ks   = Qs + 128 * 68;         // 128*68
    float* Vs   = Ks + 128 * 68;         // 64*128  (row-major)
    float* Ps   = Vs + 64 * 128;         // 64*68   (scores / probs)
    float* mrow = Ps + 64 * 68;          // 64
    float* lrow = mrow + 64;             // 64
    float* arow = lrow + 64;             // 64

    int iq = blockIdx.x, n = blockIdx.y;
    int kvh = n / GQ;
    int tid = threadIdx.x;
    int ty = tid >> 4, tx = tid & 15;
    int warp = tid >> 5, lane = tid & 31;

    // load Q tile transposed
    const float* qbase = g_q + ((size_t)n * TT + (size_t)iq * 64) * HD;
#pragma unroll
    for (int it = 0; it < 8; it++) {
        int l = tid + it * 256;
        int row = l >> 5, h4 = l & 31;
        float4 qv = *(const float4*)(qbase + (size_t)row * HD + h4 * 4);
        Qs[(h4 * 4 + 0) * 68 + row] = qv.x;
        Qs[(h4 * 4 + 1) * 68 + row] = qv.y;
        Qs[(h4 * 4 + 2) * 68 + row] = qv.z;
        Qs[(h4 * 4 + 3) * 68 + row] = qv.w;
    }
    if (tid < 64) { mrow[tid] = -3.0e38f; lrow[tid] = 0.f; }

    float acc[4][8];
#pragma unroll
    for (int i = 0; i < 4; i++)
#pragma unroll
        for (int j = 0; j < 8; j++) acc[i][j] = 0.f;

    __syncthreads();

    for (int j = 0; j <= iq; j++) {
        const float* kbase = g_k + ((size_t)kvh * TT + (size_t)j * 64) * HD;
        const float4* vb4  = (const float4*)(g_v + ((size_t)kvh * TT + (size_t)j * 64) * HD);
        float4* Vs4 = (float4*)Vs;
#pragma unroll
        for (int it = 0; it < 8; it++) {
            int l = tid + it * 256;
            int row = l >> 5, h4 = l & 31;
            float4 kvv = *(const float4*)(kbase + (size_t)row * HD + h4 * 4);
            Ks[(h4 * 4 + 0) * 68 + row] = kvv.x;
            Ks[(h4 * 4 + 1) * 68 + row] = kvv.y;
            Ks[(h4 * 4 + 2) * 68 + row] = kvv.z;
            Ks[(h4 * 4 + 3) * 68 + row] = kvv.w;
            Vs4[l] = vb4[l];
        }
        __syncthreads();

        // S = Q K^T : each thread 4 rows x 4 cols
        float sc[4][4];
#pragma unroll
        for (int i = 0; i < 4; i++)
#pragma unroll
            for (int c = 0; c < 4; c++) sc[i][c] = 0.f;

#pragma unroll 8
        for (int h = 0; h < 128; h++) {
            float4 a = *(const float4*)&Qs[h * 68 + ty * 4];
            float4 b = *(const float4*)&Ks[h * 68 + tx * 4];
            float av[4] = {a.x, a.y, a.z, a.w};
            float bv[4] = {b.x, b.y, b.z, b.w};
#pragma unroll
            for (int i = 0; i < 4; i++)
#pragma unroll
                for (int c = 0; c < 4; c++) sc[i][c] += av[i] * bv[c];
        }

        if (j == iq) {
#pragma unroll
            for (int i = 0; i < 4; i++)
#pragma unroll
                for (int c = 0; c < 4; c++)
                    if (tx * 4 + c > ty * 4 + i) sc[i][c] = -1.0e30f;
        }
#pragma unroll
        for (int i = 0; i < 4; i++)
            *(float4*)&Ps[(ty * 4 + i) * 68 + tx * 4] =
                make_float4(sc[i][0], sc[i][1], sc[i][2], sc[i][3]);
        __syncwarp();

        // row stats: warp w owns rows [8w, 8w+8)  (all written by this warp)
#pragma unroll
        for (int rr = 0; rr < 8; rr++) {
            int r = warp * 8 + rr;
            float v1 = Ps[r * 68 + lane];
            float v2 = Ps[r * 68 + 32 + lane];
            float mx = fmaxf(v1, v2);
#pragma unroll
            for (int off = 16; off > 0; off >>= 1)
                mx = fmaxf(mx, __shfl_xor_sync(0xFFFFFFFFu, mx, off));
            float m_old = mrow[r];
            float m_new = fmaxf(m_old, mx);
            float p1 = __expf(v1 - m_new);
            float p2 = __expf(v2 - m_new);
            float sum = p1 + p2;
#pragma unroll
            for (int off = 16; off > 0; off >>= 1)
                sum += __shfl_xor_sync(0xFFFFFFFFu, sum, off);
            Ps[r * 68 + lane] = p1;
            Ps[r * 68 + 32 + lane] = p2;
            if (lane == 0) {
                float al = __expf(m_old - m_new);
                arow[r] = al;
                lrow[r] = lrow[r] * al + sum;
                mrow[r] = m_new;
            }
        }
        __syncwarp();

        // rescale accumulators (rows are warp-local)
#pragma unroll
        for (int i = 0; i < 4; i++) {
            float al = arow[ty * 4 + i];
#pragma unroll
            for (int c = 0; c < 8; c++) acc[i][c] *= al;
        }

        // O += P @ V
#pragma unroll 4
        for (int kk = 0; kk < 64; kk++) {
            float p0 = Ps[(ty * 4 + 0) * 68 + kk];
            float p1 = Ps[(ty * 4 + 1) * 68 + kk];
            float p2 = Ps[(ty * 4 + 2) * 68 + kk];
            float p3 = Ps[(ty * 4 + 3) * 68 + kk];
            float4 v0 = *(const float4*)&Vs[kk * 128 + tx * 4];
            float4 v1 = *(const float4*)&Vs[kk * 128 + 64 + tx * 4];
            float vv[8] = {v0.x, v0.y, v0.z, v0.w, v1.x, v1.y, v1.z, v1.w};
            float pp[4] = {p0, p1, p2, p3};
#pragma unroll
            for (int i = 0; i < 4; i++)
#pragma unroll
                for (int c = 0; c < 8; c++) acc[i][c] += pp[i] * vv[c];
        }
        __syncthreads();
    }

    // epilogue: divide by l, write ctx[t][n*H + h]
#pragma unroll
    for (int i = 0; i < 4; i++) {
        float inv = 1.f / lrow[ty * 4 + i];
        int t = iq * 64 + ty * 4 + i;
        float4 o0 = make_float4(acc[i][0] * inv, acc[i][1] * inv, acc[i][2] * inv, acc[i][3] * inv);
        float4 o1 = make_float4(acc[i][4] * inv, acc[i][5] * inv, acc[i][6] * inv, acc[i][7] * inv);
        *(float4*)&g_ctx[(size_t)t * DD + n * HD + tx * 4] = o0;
        *(float4*)&g_ctx[(size_t)t * DD + n * HD + 64 + tx * 4] = o1;
    }
}

// ---------------------------------------------------------------------------
// Output projection: out[T,D] = ctx[T, N*H] @ wo[N*H, D]
// grid (T/64, D/128), block 256. Same tile engine as qkv proj.
// ---------------------------------------------------------------------------
__global__ __launch_bounds__(256) void out_proj_kernel(
    const float* __restrict__ wo, float* __restrict__ out)
{
    __shared__ float Xs[16][68];
    __shared__ float Ws[16 * 128];

    int t0 = blockIdx.x * 64;
    int n0 = blockIdx.y * 128;
    int tid = threadIdx.x;
    int ty = tid >> 4, tx = tid & 15;

    float acc[4][8];
#pragma unroll
    for (int i = 0; i < 4; i++)
#pragma unroll
        for (int j = 0; j < 8; j++) acc[i][j] = 0.f;

    int xrow = tid >> 2, xc4 = tid & 3;
    const float4* x4 = (const float4*)g_ctx;
    float4* Ws4 = (float4*)Ws;

    for (int k0 = 0; k0 < DD; k0 += 16) {
        float4 xv = x4[((size_t)(t0 + xrow) * DD + k0) / 4 + xc4];
        Xs[xc4 * 4 + 0][xrow] = xv.x;
        Xs[xc4 * 4 + 1][xrow] = xv.y;
        Xs[xc4 * 4 + 2][xrow] = xv.z;
        Xs[xc4 * 4 + 3][xrow] = xv.w;
#pragma unroll
        for (int it = 0; it < 2; it++) {
            int l = tid + it * 256;
            int kk = l >> 5, h4 = l & 31;
            Ws4[l] = *(const float4*)(wo + (size_t)(k0 + kk) * DD + n0 + h4 * 4);
        }
        __syncthreads();
#pragma unroll
        for (int kk = 0; kk < 16; kk++) {
            float4 a  = *(const float4*)&Xs[kk][ty * 4];
            float4 b0 = *(const float4*)&Ws[kk * 128 + tx * 4];
            float4 b1 = *(const float4*)&Ws[kk * 128 + 64 + tx * 4];
            float av[4] = {a.x, a.y, a.z, a.w};
            float bv8[8] = {b0.x, b0.y, b0.z, b0.w, b1.x, b1.y, b1.z, b1.w};
#pragma unroll
            for (int i = 0; i < 4; i++)
#pragma unroll
                for (int j = 0; j < 8; j++) acc[i][j] += av[i] * bv8[j];
        }
        __syncthreads();
    }

#pragma unroll
    for (int i = 0; i < 4; i++) {
        int t = t0 + ty * 4 + i;
        float4 o0 = make_float4(acc[i][0], acc[i][1], acc[i][2], acc[i][3]);
        float4 o1 = make_float4(acc[i][4], acc[i][5], acc[i][6], acc[i][7]);
        *(float4*)&out[(size_t)t * DD + n0 + tx * 4] = o0;
        *(float4*)&out[(size_t)t * DD + n0 + 64 + tx * 4] = o1;
    }
}

// ---------------------------------------------------------------------------

extern "C" void kernel_launch(void* const* d_in, const int* in_sizes, int n_in,
                              void* d_out, int out_size)
{
    const float* x         = (const float*)d_in[0];
    const int*   positions = (const int*)d_in[1];
    const float* wq        = (const float*)d_in[2];
    const float* bq        = (const float*)d_in[3];
    const float* wk        = (const float*)d_in[4];
    const float* bk        = (const float*)d_in[5];
    const float* wv        = (const float*)d_in[6];
    const float* bv        = (const float*)d_in[7];
    const float* wo        = (const float*)d_in[8];
    float* out = (float*)d_out;

    qkv_proj_kernel<<<dim3(TT / 64, NH + 2 * KH), 256>>>(x, wq, bq, wk, bk, wv, bv);
    rope_kernel<<<dim3(TT, NH + KH), 64>>>(positions);

    cudaFuncSetAttribute(flash_kernel, cudaFuncAttributeMaxDynamicSharedMemorySize, FLASH_SMEM);
    flash_kernel<<<dim3(TT / 64, NH), 256, FLASH_SMEM>>>();

    out_proj_kernel<<<dim3(TT / 64, DD / 128), 256>>>(wo, out);
}

// round 7
// speedup vs baseline: 1.4922x; 1.4922x over previous
#include <cuda_runtime.h>
#include <math.h>
#include <stdint.h>

#define TT 2048
#define DD 3584
#define NH 28
#define KH 4
#define HD 128
#define GQ 7

// scratch (static __device__ arrays: allocation-free)
__device__ float g_q[(size_t)NH * TT * HD];
__device__ float g_k[(size_t)KH * TT * HD];
__device__ float g_v[(size_t)KH * TT * HD];
__device__ float g_ctx[(size_t)TT * DD];

// ---------------------------------------------------------------------------
// TF32 mma.sync helpers
// ---------------------------------------------------------------------------
__device__ __forceinline__ uint32_t f2tf32(float f) {
    uint32_t r;
    asm("cvt.rna.tf32.f32 %0, %1;" : "=r"(r) : "f"(f));
    return r;
}

__device__ __forceinline__ void mma_tf32(float c[4],
                                         uint32_t a0, uint32_t a1, uint32_t a2, uint32_t a3,
                                         uint32_t b0, uint32_t b1)
{
    asm volatile(
        "mma.sync.aligned.m16n8k8.row.col.f32.tf32.tf32.f32 "
        "{%0,%1,%2,%3},{%4,%5,%6,%7},{%8,%9},{%0,%1,%2,%3};"
        : "+f"(c[0]), "+f"(c[1]), "+f"(c[2]), "+f"(c[3])
        : "r"(a0), "r"(a1), "r"(a2), "r"(a3), "r"(b0), "r"(b1));
}

// ---------------------------------------------------------------------------
// TF32 GEMM core: C[128 x 128] = X[128 x DD] * W[DD x 128](slice) (+ bias)
// X row-major ld=DD. W row-major ld=ldw, starting at column offset baked into
// Wbase. Output row-major ld=ldo.
// 256 threads = 8 warps (4 x 2). Each warp: 32 rows x 64 cols.
// Xs[row][36]: A-frag reads bank-conflict-free ((4r+c)%32).
// Ws[k][136]:  B-frag reads bank-conflict-free ((8k+n)%32).
// ---------------------------------------------------------------------------
#define XS_STRIDE 36
#define WS_STRIDE 136

template<bool HAS_BIAS>
__device__ __forceinline__ void gemm_core_tf32(
    const float* __restrict__ Xbase,
    const float* __restrict__ Wbase, int ldw,
    const float* __restrict__ bias,
    float* __restrict__ Obase, int ldo)
{
    __shared__ float Xs[128 * XS_STRIDE];   // 18432 B
    __shared__ float Ws[32 * WS_STRIDE];    // 17408 B

    int tid  = threadIdx.x;
    int warp = tid >> 5, lane = tid & 31;
    int wm = warp >> 1;        // 0..3 -> rows wm*32
    int wn = warp & 1;         // 0..1 -> cols wn*64
    int g  = lane >> 2;        // 0..7
    int tg = lane & 3;         // 0..3

    float C[2][8][4];
#pragma unroll
    for (int mt = 0; mt < 2; mt++)
#pragma unroll
        for (int nt = 0; nt < 8; nt++)
#pragma unroll
            for (int r = 0; r < 4; r++) C[mt][nt][r] = 0.f;

    for (int k0 = 0; k0 < DD; k0 += 32) {
        // stage X tile: 128 rows x 32 cols
#pragma unroll
        for (int it = 0; it < 4; it++) {
            int l = tid + it * 256;
            int row = l >> 3, c4 = l & 7;
            float4 v = *(const float4*)(Xbase + (size_t)row * DD + k0 + c4 * 4);
            *(float4*)&Xs[row * XS_STRIDE + c4 * 4] = v;
        }
        // stage W tile k-major: Ws[kk][n], 32 x 128
#pragma unroll
        for (int it = 0; it < 4; it++) {
            int l = tid + it * 256;
            int kk = l >> 5, nq = l & 31;
            float4 v = *(const float4*)(Wbase + (size_t)(k0 + kk) * ldw + nq * 4);
            *(float4*)&Ws[kk * WS_STRIDE + nq * 4] = v;
        }
        __syncthreads();

#pragma unroll
        for (int kk0 = 0; kk0 < 32; kk0 += 8) {
            uint32_t A[2][4];
#pragma unroll
            for (int mt = 0; mt < 2; mt++) {
                int rb = wm * 32 + mt * 16;
                A[mt][0] = f2tf32(Xs[(rb + g)     * XS_STRIDE + kk0 + tg]);
                A[mt][1] = f2tf32(Xs[(rb + g + 8) * XS_STRIDE + kk0 + tg]);
                A[mt][2] = f2tf32(Xs[(rb + g)     * XS_STRIDE + kk0 + tg + 4]);
                A[mt][3] = f2tf32(Xs[(rb + g + 8) * XS_STRIDE + kk0 + tg + 4]);
            }
#pragma unroll
            for (int nt = 0; nt < 8; nt++) {
                int nb = wn * 64 + nt * 8;
                uint32_t b0 = f2tf32(Ws[(kk0 + tg)     * WS_STRIDE + nb + g]);
                uint32_t b1 = f2tf32(Ws[(kk0 + tg + 4) * WS_STRIDE + nb + g]);
                mma_tf32(C[0][nt], A[0][0], A[0][1], A[0][2], A[0][3], b0, b1);
                mma_tf32(C[1][nt], A[1][0], A[1][1], A[1][2], A[1][3], b0, b1);
            }
        }
        __syncthreads();
    }

    // epilogue: C frag (r=g/g+8, c=2*tg, 2*tg+1 within tile)
#pragma unroll
    for (int mt = 0; mt < 2; mt++) {
#pragma unroll
        for (int nt = 0; nt < 8; nt++) {
            int row0 = wm * 32 + mt * 16 + g;
            int col  = wn * 64 + nt * 8 + tg * 2;
            float b0v = HAS_BIAS ? bias[col]     : 0.f;
            float b1v = HAS_BIAS ? bias[col + 1] : 0.f;
            *(float2*)&Obase[(size_t)row0 * ldo + col] =
                make_float2(C[mt][nt][0] + b0v, C[mt][nt][1] + b1v);
            *(float2*)&Obase[(size_t)(row0 + 8) * ldo + col] =
                make_float2(C[mt][nt][2] + b0v, C[mt][nt][3] + b1v);
        }
    }
}

// ---------------------------------------------------------------------------
// QKV projection (TF32 tensor cores). grid (T/128, 36), block 256.
// ---------------------------------------------------------------------------
__global__ __launch_bounds__(256, 2) void qkv_proj_tf32_kernel(
    const float* __restrict__ x,
    const float* __restrict__ wq, const float* __restrict__ bq,
    const float* __restrict__ wk, const float* __restrict__ bk,
    const float* __restrict__ wv, const float* __restrict__ bv)
{
    int z = blockIdx.y;
    const float* w; const float* b; float* out;
    if (z < NH)           { w = wq + (size_t)z * DD * HD;        b = bq + z * HD;        out = g_q + (size_t)z * TT * HD; }
    else if (z < NH + KH) { int c = z - NH;      w = wk + (size_t)c * DD * HD; b = bk + c * HD; out = g_k + (size_t)c * TT * HD; }
    else                  { int c = z - NH - KH; w = wv + (size_t)c * DD * HD; b = bv + c * HD; out = g_v + (size_t)c * TT * HD; }

    int t0 = blockIdx.x * 128;
    gemm_core_tf32<true>(x + (size_t)t0 * DD, w, HD, b, out + (size_t)t0 * HD, HD);
}

// ---------------------------------------------------------------------------
// Output projection (TF32). grid (T/128, D/128), block 256.
// ---------------------------------------------------------------------------
__global__ __launch_bounds__(256, 2) void out_proj_tf32_kernel(
    const float* __restrict__ wo, float* __restrict__ out)
{
    int t0 = blockIdx.x * 128;
    int n0 = blockIdx.y * 128;
    gemm_core_tf32<false>(g_ctx + (size_t)t0 * DD, wo + n0, DD, nullptr,
                          out + (size_t)t0 * DD + n0, DD);
}

// ---------------------------------------------------------------------------
// RoPE in-place on g_q (with 1/sqrt(H) scale) and g_k. fp64 angle math.
// grid: (T, NH+KH), block 64
// ---------------------------------------------------------------------------
__global__ void rope_kernel(const int* __restrict__ positions)
{
    int t = blockIdx.x;
    int hidx = blockIdx.y;
    int i = threadIdx.x;  // 0..63

    float* base; float scale;
    if (hidx < NH) { base = g_q + ((size_t)hidx * TT + t) * HD; scale = 0.08838834764831845f; }
    else           { base = g_k + ((size_t)(hidx - NH) * TT + t) * HD; scale = 1.0f; }

    int pos = positions[t];
    double inv_freq = pow(1000000.0, -(double)(2 * i) / 128.0);
    double ang = (double)pos * inv_freq;
    double sd, cd;
    sincos(ang, &sd, &cd);
    float c = (float)cd, s = (float)sd;
    float x1 = base[i], x2 = base[i + 64];
    base[i]      = (x1 * c - x2 * s) * scale;
    base[i + 64] = (x2 * c + x1 * s) * scale;
}

// ---------------------------------------------------------------------------
// Flash attention, fp32 (unchanged this round). grid (T/64, NH), block 256.
// ---------------------------------------------------------------------------
#define FLASH_SMEM ((128 * 68 * 2 + 64 * 128 + 64 * 68 + 192) * 4)

__global__ __launch_bounds__(256) void flash_kernel()
{
    extern __shared__ float sm[];
    float* Qs   = sm;                    // 128*68  (transposed, pad)
    float* Ks   = Qs + 128 * 68;         // 128*68
    float* Vs   = Ks + 128 * 68;         // 64*128  (row-major)
    float* Ps   = Vs + 64 * 128;         // 64*68   (scores / probs)
    float* mrow = Ps + 64 * 68;          // 64
    float* lrow = mrow + 64;             // 64
    float* arow = lrow + 64;             // 64

    int iq = blockIdx.x, n = blockIdx.y;
    int kvh = n / GQ;
    int tid = threadIdx.x;
    int ty = tid >> 4, tx = tid & 15;
    int warp = tid >> 5, lane = tid & 31;

    // load Q tile transposed
    const float* qbase = g_q + ((size_t)n * TT + (size_t)iq * 64) * HD;
#pragma unroll
    for (int it = 0; it < 8; it++) {
        int l = tid + it * 256;
        int row = l >> 5, h4 = l & 31;
        float4 qv = *(const float4*)(qbase + (size_t)row * HD + h4 * 4);
        Qs[(h4 * 4 + 0) * 68 + row] = qv.x;
        Qs[(h4 * 4 + 1) * 68 + row] = qv.y;
        Qs[(h4 * 4 + 2) * 68 + row] = qv.z;
        Qs[(h4 * 4 + 3) * 68 + row] = qv.w;
    }
    if (tid < 64) { mrow[tid] = -3.0e38f; lrow[tid] = 0.f; }

    float acc[4][8];
#pragma unroll
    for (int i = 0; i < 4; i++)
#pragma unroll
        for (int j = 0; j < 8; j++) acc[i][j] = 0.f;

    __syncthreads();

    for (int j = 0; j <= iq; j++) {
        const float* kbase = g_k + ((size_t)kvh * TT + (size_t)j * 64) * HD;
        const float4* vb4  = (const float4*)(g_v + ((size_t)kvh * TT + (size_t)j * 64) * HD);
        float4* Vs4 = (float4*)Vs;
#pragma unroll
        for (int it = 0; it < 8; it++) {
            int l = tid + it * 256;
            int row = l >> 5, h4 = l & 31;
            float4 kvv = *(const float4*)(kbase + (size_t)row * HD + h4 * 4);
            Ks[(h4 * 4 + 0) * 68 + row] = kvv.x;
            Ks[(h4 * 4 + 1) * 68 + row] = kvv.y;
            Ks[(h4 * 4 + 2) * 68 + row] = kvv.z;
            Ks[(h4 * 4 + 3) * 68 + row] = kvv.w;
            Vs4[l] = vb4[l];
        }
        __syncthreads();

        // S = Q K^T : each thread 4 rows x 4 cols
        float sc[4][4];
#pragma unroll
        for (int i = 0; i < 4; i++)
#pragma unroll
            for (int c = 0; c < 4; c++) sc[i][c] = 0.f;

#pragma unroll 8
        for (int h = 0; h < 128; h++) {
            float4 a = *(const float4*)&Qs[h * 68 + ty * 4];
            float4 b = *(const float4*)&Ks[h * 68 + tx * 4];
            float av[4] = {a.x, a.y, a.z, a.w};
            float bv[4] = {b.x, b.y, b.z, b.w};
#pragma unroll
            for (int i = 0; i < 4; i++)
#pragma unroll
                for (int c = 0; c < 4; c++) sc[i][c] += av[i] * bv[c];
        }

        if (j == iq) {
#pragma unroll
            for (int i = 0; i < 4; i++)
#pragma unroll
                for (int c = 0; c < 4; c++)
                    if (tx * 4 + c > ty * 4 + i) sc[i][c] = -1.0e30f;
        }
#pragma unroll
        for (int i = 0; i < 4; i++)
            *(float4*)&Ps[(ty * 4 + i) * 68 + tx * 4] =
                make_float4(sc[i][0], sc[i][1], sc[i][2], sc[i][3]);
        __syncwarp();

        // row stats: warp w owns rows [8w, 8w+8)
#pragma unroll
        for (int rr = 0; rr < 8; rr++) {
            int r = warp * 8 + rr;
            float v1 = Ps[r * 68 + lane];
            float v2 = Ps[r * 68 + 32 + lane];
            float mx = fmaxf(v1, v2);
#pragma unroll
            for (int off = 16; off > 0; off >>= 1)
                mx = fmaxf(mx, __shfl_xor_sync(0xFFFFFFFFu, mx, off));
            float m_old = mrow[r];
            float m_new = fmaxf(m_old, mx);
            float p1 = __expf(v1 - m_new);
            float p2 = __expf(v2 - m_new);
            float sum = p1 + p2;
#pragma unroll
            for (int off = 16; off > 0; off >>= 1)
                sum += __shfl_xor_sync(0xFFFFFFFFu, sum, off);
            Ps[r * 68 + lane] = p1;
            Ps[r * 68 + 32 + lane] = p2;
            if (lane == 0) {
                float al = __expf(m_old - m_new);
                arow[r] = al;
                lrow[r] = lrow[r] * al + sum;
                mrow[r] = m_new;
            }
        }
        __syncwarp();

        // rescale accumulators (rows are warp-local)
#pragma unroll
        for (int i = 0; i < 4; i++) {
            float al = arow[ty * 4 + i];
#pragma unroll
            for (int c = 0; c < 8; c++) acc[i][c] *= al;
        }

        // O += P @ V
#pragma unroll 4
        for (int kk = 0; kk < 64; kk++) {
            float p0 = Ps[(ty * 4 + 0) * 68 + kk];
            float p1 = Ps[(ty * 4 + 1) * 68 + kk];
            float p2 = Ps[(ty * 4 + 2) * 68 + kk];
            float p3 = Ps[(ty * 4 + 3) * 68 + kk];
            float4 v0 = *(const float4*)&Vs[kk * 128 + tx * 4];
            float4 v1 = *(const float4*)&Vs[kk * 128 + 64 + tx * 4];
            float vv[8] = {v0.x, v0.y, v0.z, v0.w, v1.x, v1.y, v1.z, v1.w};
            float pp[4] = {p0, p1, p2, p3};
#pragma unroll
            for (int i = 0; i < 4; i++)
#pragma unroll
                for (int c = 0; c < 8; c++) acc[i][c] += pp[i] * vv[c];
        }
        __syncthreads();
    }

    // epilogue: divide by l, write ctx[t][n*H + h]
#pragma unroll
    for (int i = 0; i < 4; i++) {
        float inv = 1.f / lrow[ty * 4 + i];
        int t = iq * 64 + ty * 4 + i;
        float4 o0 = make_float4(acc[i][0] * inv, acc[i][1] * inv, acc[i][2] * inv, acc[i][3] * inv);
        float4 o1 = make_float4(acc[i][4] * inv, acc[i][5] * inv, acc[i][6] * inv, acc[i][7] * inv);
        *(float4*)&g_ctx[(size_t)t * DD + n * HD + tx * 4] = o0;
        *(float4*)&g_ctx[(size_t)t * DD + n * HD + 64 + tx * 4] = o1;
    }
}

// ---------------------------------------------------------------------------

extern "C" void kernel_launch(void* const* d_in, const int* in_sizes, int n_in,
                              void* d_out, int out_size)
{
    const float* x         = (const float*)d_in[0];
    const int*   positions = (const int*)d_in[1];
    const float* wq        = (const float*)d_in[2];
    const float* bq        = (const float*)d_in[3];
    const float* wk        = (const float*)d_in[4];
    const float* bk        = (const float*)d_in[5];
    const float* wv        = (const float*)d_in[6];
    const float* bv        = (const float*)d_in[7];
    const float* wo        = (const float*)d_in[8];
    float* out = (float*)d_out;

    qkv_proj_tf32_kernel<<<dim3(TT / 128, NH + 2 * KH), 256>>>(x, wq, bq, wk, bk, wv, bv);
    rope_kernel<<<dim3(TT, NH + KH), 64>>>(positions);

    cudaFuncSetAttribute(flash_kernel, cudaFuncAttributeMaxDynamicSharedMemorySize, FLASH_SMEM);
    flash_kernel<<<dim3(TT / 64, NH), 256, FLASH_SMEM>>>();

    out_proj_tf32_kernel<<<dim3(TT / 64 / 2, DD / 128), 256>>>(wo, out);
}